// round 1
// baseline (speedup 1.0000x reference)
#include <cuda_runtime.h>
#include <math.h>

// ---------------- problem constants ----------------
#define T_      1024
#define H_      2048
#define I_      1024
#define E_      16
#define TWOI_   2048
#define G_      4
#define EPG_    4     // experts per group
#define TOPKG_  2
#define TOPK_   4
#define NPAIR_  (T_*TOPK_)   // 4096
#define ROUTED_SCALE_ 2.5f

// ---------------- device scratch (no allocations allowed) ----------------
__device__ float d_gu  [(size_t)NPAIR_*TWOI_]; // routed gate_up outputs (by slot t*4+k)
__device__ float d_act [(size_t)NPAIR_*I_];    // routed silu*u*weight (by slot)
__device__ float d_yrt [(size_t)NPAIR_*H_];    // routed down outputs (by slot)
__device__ float d_sgu [(size_t)T_*TWOI_];     // shared gate_up outputs
__device__ float d_sact[(size_t)T_*I_];        // shared silu*u
__device__ float d_sy  [(size_t)T_*H_];        // shared down outputs
__device__ int   d_cnt [E_];                   // tokens per expert
__device__ int   d_tok [E_*T_];                // gather: token index per expert entry
__device__ int   d_dst [E_*T_];                // scatter: slot (t*4+k) per expert entry
__device__ float d_wslot[NPAIR_];              // routing weight per slot

// ---------------- small kernels ----------------
__global__ void zero_cnt_kernel() {
    if (threadIdx.x < E_) d_cnt[threadIdx.x] = 0;
}

// One block per token. 16 warps -> 16 expert logits, then thread 0 does
// grouped top-k exactly like the reference.
__global__ void router_kernel(const float* __restrict__ x,
                              const float* __restrict__ gate_w,
                              const float* __restrict__ e_bias) {
    int t = blockIdx.x;
    int warp = threadIdx.x >> 5;
    int lane = threadIdx.x & 31;
    const float* xr = x + (size_t)t * H_;
    const float* wr = gate_w + (size_t)warp * H_;
    float s = 0.f;
    for (int h = lane; h < H_; h += 32) s += xr[h] * wr[h];
    #pragma unroll
    for (int o = 16; o; o >>= 1) s += __shfl_xor_sync(0xFFFFFFFFu, s, o);
    __shared__ float logit[E_];
    if (lane == 0) logit[warp] = s;
    __syncthreads();
    if (threadIdx.x == 0) {
        float sc[E_], sb[E_];
        #pragma unroll
        for (int e = 0; e < E_; e++) {
            sc[e] = 1.f / (1.f + expf(-logit[e]));
            sb[e] = sc[e] + e_bias[e];
        }
        // group scores = sum of top-2 biased scores within each group of 4
        float gs[G_];
        #pragma unroll
        for (int g = 0; g < G_; g++) {
            float m1 = -INFINITY, m2 = -INFINITY;
            #pragma unroll
            for (int i = 0; i < EPG_; i++) {
                float v = sb[g*EPG_ + i];
                if (v > m1) { m2 = m1; m1 = v; }
                else if (v > m2) { m2 = v; }
            }
            gs[g] = m1 + m2;
        }
        // top-2 groups (ties -> lower index, like lax.top_k)
        int g1 = 0;
        for (int g = 1; g < G_; g++) if (gs[g] > gs[g1]) g1 = g;
        int g2 = -1;
        for (int g = 0; g < G_; g++) {
            if (g == g1) continue;
            if (g2 < 0 || gs[g] > gs[g2]) g2 = g;
        }
        // masked biased scores (masked-out -> 0.0, exactly like the reference)
        float tmp[E_];
        #pragma unroll
        for (int e = 0; e < E_; e++) {
            int g = e / EPG_;
            tmp[e] = (g == g1 || g == g2) ? sb[e] : 0.f;
        }
        // top-4 of tmp (ties -> lower index), weights from UNbiased scores
        bool taken[E_];
        #pragma unroll
        for (int e = 0; e < E_; e++) taken[e] = false;
        int ids[TOPK_]; float wv[TOPK_]; float wsum = 0.f;
        #pragma unroll
        for (int k = 0; k < TOPK_; k++) {
            int bi = -1; float bv = -INFINITY;
            for (int e = 0; e < E_; e++) {
                if (!taken[e] && tmp[e] > bv) { bv = tmp[e]; bi = e; }
            }
            taken[bi] = true;
            ids[k] = bi;
            wv[k] = sc[bi];
            wsum += wv[k];
        }
        float inv = 1.f / wsum;
        #pragma unroll
        for (int k = 0; k < TOPK_; k++) {
            int e = ids[k];
            int pos = atomicAdd(&d_cnt[e], 1);
            d_tok[e*T_ + pos] = t;
            d_dst[e*T_ + pos] = t*TOPK_ + k;
            d_wslot[t*TOPK_ + k] = wv[k] * inv;
        }
    }
}

// ---------------- generic TN SGEMM: C[M,N] = A[M,K] * B[N,K]^T ----------------
// 128x128 tile, K-step 8, 256 threads, 8x8 per thread.
// GATHER_A: A row index = gatherA[e*T_ + m]; SCATTER_C: C row = scatterC[e*T_ + m].
// EXPERT: e = blockIdx.z, M = counts[e], B advances by strideB per expert.
template<bool GATHER_A, bool SCATTER_C, bool EXPERT>
__global__ void __launch_bounds__(256)
sgemm_tn(const float* __restrict__ Abase, int lda,
         const float* __restrict__ Bbase, int ldb, long strideB,
         float* __restrict__ Cbase, int ldc,
         int Mfixed, const int* __restrict__ counts,
         const int* __restrict__ gatherA,
         const int* __restrict__ scatterC,
         int K)
{
    const int e = EXPERT ? blockIdx.z : 0;
    const int M = EXPERT ? counts[e] : Mfixed;
    const int m0 = blockIdx.y * 128;
    if (m0 >= M) return;
    const int n0 = blockIdx.x * 128;

    const float* B = Bbase + (long)e * strideB;

    __shared__ float As[8][132];
    __shared__ float Bs[8][132];

    const int tid  = threadIdx.x;
    const int lrow = tid >> 1;        // 0..127
    const int lk   = (tid & 1) * 4;   // 0 or 4

    const bool a_ok = (m0 + lrow) < M;
    long arow = 0;
    if (a_ok) arow = GATHER_A ? (long)gatherA[e*T_ + m0 + lrow] : (long)(m0 + lrow);
    const float* Aptr = Abase + arow * lda + lk;
    const float* Bptr = B + (long)(n0 + lrow) * ldb + lk;

    const int ty = tid >> 4;      // 0..15
    const int tx = tid & 15;      // 0..15
    const int mr = ty * 8;
    const int nc = tx * 8;

    float acc[8][8];
    #pragma unroll
    for (int i = 0; i < 8; i++)
        #pragma unroll
        for (int j = 0; j < 8; j++) acc[i][j] = 0.f;

    for (int k0 = 0; k0 < K; k0 += 8) {
        float4 av = a_ok ? *(const float4*)(Aptr + k0) : make_float4(0.f,0.f,0.f,0.f);
        float4 bv = *(const float4*)(Bptr + k0);
        __syncthreads();
        As[lk+0][lrow] = av.x; As[lk+1][lrow] = av.y;
        As[lk+2][lrow] = av.z; As[lk+3][lrow] = av.w;
        Bs[lk+0][lrow] = bv.x; Bs[lk+1][lrow] = bv.y;
        Bs[lk+2][lrow] = bv.z; Bs[lk+3][lrow] = bv.w;
        __syncthreads();
        #pragma unroll
        for (int kk = 0; kk < 8; kk++) {
            float a0[8], b0[8];
            *(float4*)&a0[0] = *(const float4*)&As[kk][mr];
            *(float4*)&a0[4] = *(const float4*)&As[kk][mr+4];
            *(float4*)&b0[0] = *(const float4*)&Bs[kk][nc];
            *(float4*)&b0[4] = *(const float4*)&Bs[kk][nc+4];
            #pragma unroll
            for (int i = 0; i < 8; i++)
                #pragma unroll
                for (int j = 0; j < 8; j++)
                    acc[i][j] = fmaf(a0[i], b0[j], acc[i][j]);
        }
    }

    #pragma unroll
    for (int i = 0; i < 8; i++) {
        int lm = m0 + mr + i;
        if (lm < M) {
            long crow = SCATTER_C ? (long)scatterC[e*T_ + lm] : (long)lm;
            float* Cp = Cbase + crow * ldc + n0 + nc;
            *(float4*)Cp       = *(float4*)&acc[i][0];
            *(float4*)(Cp + 4) = *(float4*)&acc[i][4];
        }
    }
}

// ---------------- silu-and-mul ----------------
__global__ void silu_shared_kernel() {
    int idx = blockIdx.x * blockDim.x + threadIdx.x;   // over T_*I_/4
    if (idx >= T_*I_/4) return;
    int row = idx / (I_/4);
    int j4  = (idx % (I_/4)) * 4;
    const float4 g = *(const float4*)&d_sgu[(size_t)row*TWOI_ + j4];
    const float4 u = *(const float4*)&d_sgu[(size_t)row*TWOI_ + I_ + j4];
    float4 r;
    r.x = (g.x / (1.f + expf(-g.x))) * u.x;
    r.y = (g.y / (1.f + expf(-g.y))) * u.y;
    r.z = (g.z / (1.f + expf(-g.z))) * u.z;
    r.w = (g.w / (1.f + expf(-g.w))) * u.w;
    *(float4*)&d_sact[(size_t)row*I_ + j4] = r;
}

__global__ void silu_routed_kernel() {
    int idx = blockIdx.x * blockDim.x + threadIdx.x;   // over NPAIR_*I_/4
    if (idx >= NPAIR_*I_/4) return;
    int slot = idx / (I_/4);
    int j4   = (idx % (I_/4)) * 4;
    const float4 g = *(const float4*)&d_gu[(size_t)slot*TWOI_ + j4];
    const float4 u = *(const float4*)&d_gu[(size_t)slot*TWOI_ + I_ + j4];
    float w = d_wslot[slot];
    float4 r;
    r.x = w * (g.x / (1.f + expf(-g.x))) * u.x;
    r.y = w * (g.y / (1.f + expf(-g.y))) * u.y;
    r.z = w * (g.z / (1.f + expf(-g.z))) * u.z;
    r.w = w * (g.w / (1.f + expf(-g.w))) * u.w;
    *(float4*)&d_act[(size_t)slot*I_ + j4] = r;
}

// ---------------- final combine ----------------
__global__ void reduce_kernel(float* __restrict__ out) {
    int idx = blockIdx.x * blockDim.x + threadIdx.x;   // over T_*H_/4
    if (idx >= T_*H_/4) return;
    int t  = idx / (H_/4);
    int h4 = (idx % (H_/4)) * 4;
    float4 s  = *(const float4*)&d_sy[(size_t)t*H_ + h4];
    float4 y0 = *(const float4*)&d_yrt[((size_t)t*TOPK_ + 0)*H_ + h4];
    float4 y1 = *(const float4*)&d_yrt[((size_t)t*TOPK_ + 1)*H_ + h4];
    float4 y2 = *(const float4*)&d_yrt[((size_t)t*TOPK_ + 2)*H_ + h4];
    float4 y3 = *(const float4*)&d_yrt[((size_t)t*TOPK_ + 3)*H_ + h4];
    float4 r;
    r.x = s.x + ROUTED_SCALE_ * (y0.x + y1.x + y2.x + y3.x);
    r.y = s.y + ROUTED_SCALE_ * (y0.y + y1.y + y2.y + y3.y);
    r.z = s.z + ROUTED_SCALE_ * (y0.z + y1.z + y2.z + y3.z);
    r.w = s.w + ROUTED_SCALE_ * (y0.w + y1.w + y2.w + y3.w);
    *(float4*)&out[(size_t)t*H_ + h4] = r;
}

// ---------------- launcher ----------------
extern "C" void kernel_launch(void* const* d_in, const int* in_sizes, int n_in,
                              void* d_out, int out_size) {
    const float* x        = (const float*)d_in[0];  // [T,H]
    const float* gate_w   = (const float*)d_in[1];  // [E,H]
    const float* e_bias   = (const float*)d_in[2];  // [E]
    const float* w_gu     = (const float*)d_in[3];  // [E,2I,H]
    const float* w_dn     = (const float*)d_in[4];  // [E,H,I]
    const float* s_wgu    = (const float*)d_in[5];  // [2I,H]
    const float* s_wdn    = (const float*)d_in[6];  // [H,I]
    float* out = (float*)d_out;

    // symbol addresses for generic GEMM arguments
    float *p_gu, *p_act, *p_yrt, *p_sgu, *p_sact, *p_sy;
    int *p_cnt, *p_tok, *p_dst;
    cudaGetSymbolAddress((void**)&p_gu,   d_gu);
    cudaGetSymbolAddress((void**)&p_act,  d_act);
    cudaGetSymbolAddress((void**)&p_yrt,  d_yrt);
    cudaGetSymbolAddress((void**)&p_sgu,  d_sgu);
    cudaGetSymbolAddress((void**)&p_sact, d_sact);
    cudaGetSymbolAddress((void**)&p_sy,   d_sy);
    cudaGetSymbolAddress((void**)&p_cnt,  d_cnt);
    cudaGetSymbolAddress((void**)&p_tok,  d_tok);
    cudaGetSymbolAddress((void**)&p_dst,  d_dst);

    // 1. reset expert counters
    zero_cnt_kernel<<<1, 32>>>();

    // 2. router + gather-list construction
    router_kernel<<<T_, 512>>>(x, gate_w, e_bias);

    // 3. shared expert: gate_up GEMM  [T,H] x [2I,H]^T -> [T,2I]
    sgemm_tn<false,false,false><<<dim3(TWOI_/128, T_/128, 1), 256>>>(
        x, H_, s_wgu, H_, 0, p_sgu, TWOI_, T_, p_cnt, p_tok, p_dst, H_);

    // 4. shared silu*mul
    silu_shared_kernel<<<(T_*I_/4 + 255)/256, 256>>>();

    // 5. shared expert: down GEMM  [T,I] x [H,I]^T -> [T,H]
    sgemm_tn<false,false,false><<<dim3(H_/128, T_/128, 1), 256>>>(
        p_sact, I_, s_wdn, I_, 0, p_sy, H_, T_, p_cnt, p_tok, p_dst, I_);

    // 6. routed gate_up: gather tokens per expert, scatter to pair slots
    sgemm_tn<true,true,true><<<dim3(TWOI_/128, T_/128, E_), 256>>>(
        x, H_, w_gu, H_, (long)TWOI_*H_, p_gu, TWOI_, 0, p_cnt, p_tok, p_dst, H_);

    // 7. routed silu*mul*weight
    silu_routed_kernel<<<(NPAIR_*I_/4 + 255)/256, 256>>>();

    // 8. routed down: gather act rows by slot, scatter outputs by slot
    sgemm_tn<true,true,true><<<dim3(H_/128, T_/128, E_), 256>>>(
        p_act, I_, w_dn, I_, (long)H_*I_, p_yrt, H_, 0, p_cnt, p_dst, p_dst, I_);

    // 9. combine: out = shared + 2.5 * sum_k routed
    reduce_kernel<<<(T_*H_/4 + 255)/256, 256>>>(out);
}

// round 2
// speedup vs baseline: 2.2326x; 2.2326x over previous
#include <cuda_runtime.h>
#include <math.h>

// ---------------- problem constants ----------------
#define T_      1024
#define H_      2048
#define I_      1024
#define E_      16
#define TWOI_   2048
#define G_      4
#define EPG_    4     // experts per group
#define TOPK_   4
#define NPAIR_  (T_*TOPK_)   // 4096
#define ROUTED_SCALE_ 2.5f

// ---------------- device scratch (no allocations allowed) ----------------
__device__ float d_gu  [(size_t)NPAIR_*TWOI_]; // routed gate_up outputs (by slot t*4+k)
__device__ float d_act [(size_t)NPAIR_*I_];    // routed silu*u*weight (by slot)
__device__ float d_yrt [(size_t)NPAIR_*H_];    // routed down outputs (by slot)
__device__ float d_sgu [(size_t)T_*TWOI_];     // shared gate_up outputs
__device__ float d_sact[(size_t)T_*I_];        // shared silu*u
__device__ float d_sy  [(size_t)T_*H_];        // shared down outputs
__device__ int   d_cnt [E_];                   // tokens per expert
__device__ int   d_tok [E_*T_];                // gather: token index per expert entry
__device__ int   d_dst [E_*T_];                // scatter: slot (t*4+k) per expert entry
__device__ float d_wslot[NPAIR_];              // routing weight per slot

// ---------------- small kernels ----------------
__global__ void zero_cnt_kernel() {
    if (threadIdx.x < E_) d_cnt[threadIdx.x] = 0;
}

// One block per token. 16 warps -> 16 expert logits (fp32 exact — routing
// decisions must not be perturbed by low precision), then thread 0 does
// grouped top-k exactly like the reference.
__global__ void router_kernel(const float* __restrict__ x,
                              const float* __restrict__ gate_w,
                              const float* __restrict__ e_bias) {
    int t = blockIdx.x;
    int warp = threadIdx.x >> 5;
    int lane = threadIdx.x & 31;
    const float* xr = x + (size_t)t * H_;
    const float* wr = gate_w + (size_t)warp * H_;
    float s = 0.f;
    for (int h = lane; h < H_; h += 32) s += xr[h] * wr[h];
    #pragma unroll
    for (int o = 16; o; o >>= 1) s += __shfl_xor_sync(0xFFFFFFFFu, s, o);
    __shared__ float logit[E_];
    if (lane == 0) logit[warp] = s;
    __syncthreads();
    if (threadIdx.x == 0) {
        float sc[E_], sb[E_];
        #pragma unroll
        for (int e = 0; e < E_; e++) {
            sc[e] = 1.f / (1.f + expf(-logit[e]));
            sb[e] = sc[e] + e_bias[e];
        }
        float gs[G_];
        #pragma unroll
        for (int g = 0; g < G_; g++) {
            float m1 = -INFINITY, m2 = -INFINITY;
            #pragma unroll
            for (int i = 0; i < EPG_; i++) {
                float v = sb[g*EPG_ + i];
                if (v > m1) { m2 = m1; m1 = v; }
                else if (v > m2) { m2 = v; }
            }
            gs[g] = m1 + m2;
        }
        int g1 = 0;
        for (int g = 1; g < G_; g++) if (gs[g] > gs[g1]) g1 = g;
        int g2 = -1;
        for (int g = 0; g < G_; g++) {
            if (g == g1) continue;
            if (g2 < 0 || gs[g] > gs[g2]) g2 = g;
        }
        float tmp[E_];
        #pragma unroll
        for (int e = 0; e < E_; e++) {
            int g = e / EPG_;
            tmp[e] = (g == g1 || g == g2) ? sb[e] : 0.f;
        }
        bool taken[E_];
        #pragma unroll
        for (int e = 0; e < E_; e++) taken[e] = false;
        int ids[TOPK_]; float wv[TOPK_]; float wsum = 0.f;
        #pragma unroll
        for (int k = 0; k < TOPK_; k++) {
            int bi = -1; float bv = -INFINITY;
            for (int e = 0; e < E_; e++) {
                if (!taken[e] && tmp[e] > bv) { bv = tmp[e]; bi = e; }
            }
            taken[bi] = true;
            ids[k] = bi;
            wv[k] = sc[bi];
            wsum += wv[k];
        }
        float inv = 1.f / wsum;
        #pragma unroll
        for (int k = 0; k < TOPK_; k++) {
            int e = ids[k];
            int pos = atomicAdd(&d_cnt[e], 1);
            d_tok[e*T_ + pos] = t;
            d_dst[e*T_ + pos] = t*TOPK_ + k;
            d_wslot[t*TOPK_ + k] = wv[k] * inv;
        }
    }
}

// ---------------- tf32 helpers ----------------
__device__ __forceinline__ unsigned f2tf32(float x) {
    unsigned y;
    asm("cvt.rna.tf32.f32 %0, %1;" : "=r"(y) : "f"(x));
    return y;
}

__device__ __forceinline__ void mma_tf32(float c[4], const unsigned a[4], const unsigned b[2]) {
    asm volatile(
        "mma.sync.aligned.m16n8k8.row.col.f32.tf32.tf32.f32 "
        "{%0,%1,%2,%3}, {%4,%5,%6,%7}, {%8,%9}, {%0,%1,%2,%3};"
        : "+f"(c[0]), "+f"(c[1]), "+f"(c[2]), "+f"(c[3])
        : "r"(a[0]), "r"(a[1]), "r"(a[2]), "r"(a[3]), "r"(b[0]), "r"(b[1]));
}

// ---------------- tensor-core TN GEMM: C[M,N] = A[M,K] * B[N,K]^T ----------------
// 128x128 tile, BK=16, 256 threads = 8 warps in 4(M)x2(N), warp tile 32x64.
// tf32 mma.sync m16n8k8, fp32 accumulate.
// GATHER_A: A row = gatherA[e*T_ + m]; SCATTER_C: C row = scatterC[e*T_ + m].
// EXPERT: e = blockIdx.z, M = counts[e], B advances by strideB per expert.
template<bool GATHER_A, bool SCATTER_C, bool EXPERT>
__global__ void __launch_bounds__(256, 2)
mma_gemm_tn(const float* __restrict__ Abase, int lda,
            const float* __restrict__ Bbase, int ldb, long strideB,
            float* __restrict__ Cbase, int ldc,
            int Mfixed, const int* __restrict__ counts,
            const int* __restrict__ gatherA,
            const int* __restrict__ scatterC,
            int K)
{
    const int e = EXPERT ? blockIdx.z : 0;
    const int M = EXPERT ? counts[e] : Mfixed;
    const int m0 = blockIdx.y * 128;
    if (m0 >= M) return;
    const int n0 = blockIdx.x * 128;

    const float* B = Bbase + (long)e * strideB;

    // row stride 136 words: (k*136 + m) mod 32 = (k*8 + m) mod 32 ->
    // fragment loads (4 distinct k) x (8 distinct m/n) cover all 32 banks.
    __shared__ unsigned As[16][136];
    __shared__ unsigned Bs[16][136];

    const int tid  = threadIdx.x;
    const int lane = tid & 31;
    const int warp = tid >> 5;
    const int wm   = warp >> 1;         // 0..3  (M direction, 32 rows each)
    const int wn   = warp & 1;          // 0..1  (N direction, 64 cols each)
    const int g    = lane >> 2;         // groupID 0..7
    const int tg   = lane & 3;          // thread-in-group 0..3

    // global staging: each thread owns smem row (tid>>1), k-halves per (tid&1)
    const int lrow = tid >> 1;          // 0..127
    const int koff = (tid & 1) * 8;     // 0 or 8

    const bool a_ok = (m0 + lrow) < M;
    long arow = 0;
    if (a_ok) arow = GATHER_A ? (long)gatherA[e*T_ + m0 + lrow] : (long)(m0 + lrow);
    const float* Aptr = Abase + arow * lda + koff;
    const float* Bptr = B + (long)(n0 + lrow) * ldb + koff;

    float acc[2][8][4];
    #pragma unroll
    for (int mt = 0; mt < 2; mt++)
        #pragma unroll
        for (int nt = 0; nt < 8; nt++)
            #pragma unroll
            for (int i = 0; i < 4; i++) acc[mt][nt][i] = 0.f;

    for (int k0 = 0; k0 < K; k0 += 16) {
        float4 av0 = a_ok ? *(const float4*)(Aptr + k0)     : make_float4(0.f,0.f,0.f,0.f);
        float4 av1 = a_ok ? *(const float4*)(Aptr + k0 + 4) : make_float4(0.f,0.f,0.f,0.f);
        float4 bv0 = *(const float4*)(Bptr + k0);
        float4 bv1 = *(const float4*)(Bptr + k0 + 4);
        __syncthreads();
        As[koff+0][lrow] = f2tf32(av0.x); As[koff+1][lrow] = f2tf32(av0.y);
        As[koff+2][lrow] = f2tf32(av0.z); As[koff+3][lrow] = f2tf32(av0.w);
        As[koff+4][lrow] = f2tf32(av1.x); As[koff+5][lrow] = f2tf32(av1.y);
        As[koff+6][lrow] = f2tf32(av1.z); As[koff+7][lrow] = f2tf32(av1.w);
        Bs[koff+0][lrow] = f2tf32(bv0.x); Bs[koff+1][lrow] = f2tf32(bv0.y);
        Bs[koff+2][lrow] = f2tf32(bv0.z); Bs[koff+3][lrow] = f2tf32(bv0.w);
        Bs[koff+4][lrow] = f2tf32(bv1.x); Bs[koff+5][lrow] = f2tf32(bv1.y);
        Bs[koff+6][lrow] = f2tf32(bv1.z); Bs[koff+7][lrow] = f2tf32(bv1.w);
        __syncthreads();

        #pragma unroll
        for (int ks = 0; ks < 16; ks += 8) {
            unsigned a[2][4], b[8][2];
            #pragma unroll
            for (int mt = 0; mt < 2; mt++) {
                int mb = wm*32 + mt*16;
                a[mt][0] = As[ks+tg  ][mb + g    ];
                a[mt][1] = As[ks+tg  ][mb + g + 8];
                a[mt][2] = As[ks+tg+4][mb + g    ];
                a[mt][3] = As[ks+tg+4][mb + g + 8];
            }
            #pragma unroll
            for (int nt = 0; nt < 8; nt++) {
                int nb = wn*64 + nt*8;
                b[nt][0] = Bs[ks+tg  ][nb + g];
                b[nt][1] = Bs[ks+tg+4][nb + g];
            }
            #pragma unroll
            for (int mt = 0; mt < 2; mt++)
                #pragma unroll
                for (int nt = 0; nt < 8; nt++)
                    mma_tf32(acc[mt][nt], a[mt], b[nt]);
        }
    }

    // epilogue: c0,c1 -> row g, cols 2tg,2tg+1 ; c2,c3 -> row g+8
    #pragma unroll
    for (int mt = 0; mt < 2; mt++) {
        #pragma unroll
        for (int half = 0; half < 2; half++) {
            int lm = m0 + wm*32 + mt*16 + g + half*8;
            if (lm < M) {
                long crow = SCATTER_C ? (long)scatterC[e*T_ + lm] : (long)lm;
                float* Cp = Cbase + crow * ldc + n0 + wn*64 + 2*tg;
                #pragma unroll
                for (int nt = 0; nt < 8; nt++) {
                    float2 v;
                    v.x = acc[mt][nt][half*2 + 0];
                    v.y = acc[mt][nt][half*2 + 1];
                    *(float2*)(Cp + nt*8) = v;
                }
            }
        }
    }
}

// ---------------- silu-and-mul ----------------
__global__ void silu_shared_kernel() {
    int idx = blockIdx.x * blockDim.x + threadIdx.x;   // over T_*I_/4
    if (idx >= T_*I_/4) return;
    int row = idx / (I_/4);
    int j4  = (idx % (I_/4)) * 4;
    const float4 g = *(const float4*)&d_sgu[(size_t)row*TWOI_ + j4];
    const float4 u = *(const float4*)&d_sgu[(size_t)row*TWOI_ + I_ + j4];
    float4 r;
    r.x = (g.x / (1.f + expf(-g.x))) * u.x;
    r.y = (g.y / (1.f + expf(-g.y))) * u.y;
    r.z = (g.z / (1.f + expf(-g.z))) * u.z;
    r.w = (g.w / (1.f + expf(-g.w))) * u.w;
    *(float4*)&d_sact[(size_t)row*I_ + j4] = r;
}

__global__ void silu_routed_kernel() {
    int idx = blockIdx.x * blockDim.x + threadIdx.x;   // over NPAIR_*I_/4
    if (idx >= NPAIR_*I_/4) return;
    int slot = idx / (I_/4);
    int j4   = (idx % (I_/4)) * 4;
    const float4 g = *(const float4*)&d_gu[(size_t)slot*TWOI_ + j4];
    const float4 u = *(const float4*)&d_gu[(size_t)slot*TWOI_ + I_ + j4];
    float w = d_wslot[slot];
    float4 r;
    r.x = w * (g.x / (1.f + expf(-g.x))) * u.x;
    r.y = w * (g.y / (1.f + expf(-g.y))) * u.y;
    r.z = w * (g.z / (1.f + expf(-g.z))) * u.z;
    r.w = w * (g.w / (1.f + expf(-g.w))) * u.w;
    *(float4*)&d_act[(size_t)slot*I_ + j4] = r;
}

// ---------------- final combine ----------------
__global__ void reduce_kernel(float* __restrict__ out) {
    int idx = blockIdx.x * blockDim.x + threadIdx.x;   // over T_*H_/4
    if (idx >= T_*H_/4) return;
    int t  = idx / (H_/4);
    int h4 = (idx % (H_/4)) * 4;
    float4 s  = *(const float4*)&d_sy[(size_t)t*H_ + h4];
    float4 y0 = *(const float4*)&d_yrt[((size_t)t*TOPK_ + 0)*H_ + h4];
    float4 y1 = *(const float4*)&d_yrt[((size_t)t*TOPK_ + 1)*H_ + h4];
    float4 y2 = *(const float4*)&d_yrt[((size_t)t*TOPK_ + 2)*H_ + h4];
    float4 y3 = *(const float4*)&d_yrt[((size_t)t*TOPK_ + 3)*H_ + h4];
    float4 r;
    r.x = s.x + ROUTED_SCALE_ * (y0.x + y1.x + y2.x + y3.x);
    r.y = s.y + ROUTED_SCALE_ * (y0.y + y1.y + y2.y + y3.y);
    r.z = s.z + ROUTED_SCALE_ * (y0.z + y1.z + y2.z + y3.z);
    r.w = s.w + ROUTED_SCALE_ * (y0.w + y1.w + y2.w + y3.w);
    *(float4*)&out[(size_t)t*H_ + h4] = r;
}

// ---------------- launcher ----------------
extern "C" void kernel_launch(void* const* d_in, const int* in_sizes, int n_in,
                              void* d_out, int out_size) {
    const float* x        = (const float*)d_in[0];  // [T,H]
    const float* gate_w   = (const float*)d_in[1];  // [E,H]
    const float* e_bias   = (const float*)d_in[2];  // [E]
    const float* w_gu     = (const float*)d_in[3];  // [E,2I,H]
    const float* w_dn     = (const float*)d_in[4];  // [E,H,I]
    const float* s_wgu    = (const float*)d_in[5];  // [2I,H]
    const float* s_wdn    = (const float*)d_in[6];  // [H,I]
    float* out = (float*)d_out;

    float *p_gu, *p_act, *p_yrt, *p_sgu, *p_sact, *p_sy;
    int *p_cnt, *p_tok, *p_dst;
    cudaGetSymbolAddress((void**)&p_gu,   d_gu);
    cudaGetSymbolAddress((void**)&p_act,  d_act);
    cudaGetSymbolAddress((void**)&p_yrt,  d_yrt);
    cudaGetSymbolAddress((void**)&p_sgu,  d_sgu);
    cudaGetSymbolAddress((void**)&p_sact, d_sact);
    cudaGetSymbolAddress((void**)&p_sy,   d_sy);
    cudaGetSymbolAddress((void**)&p_cnt,  d_cnt);
    cudaGetSymbolAddress((void**)&p_tok,  d_tok);
    cudaGetSymbolAddress((void**)&p_dst,  d_dst);

    // 1. reset expert counters
    zero_cnt_kernel<<<1, 32>>>();

    // 2. router + gather-list construction (fp32 exact)
    router_kernel<<<T_, 512>>>(x, gate_w, e_bias);

    // 3. shared expert: gate_up GEMM  [T,H] x [2I,H]^T -> [T,2I]
    mma_gemm_tn<false,false,false><<<dim3(TWOI_/128, T_/128, 1), 256>>>(
        x, H_, s_wgu, H_, 0, p_sgu, TWOI_, T_, p_cnt, p_tok, p_dst, H_);

    // 4. shared silu*mul
    silu_shared_kernel<<<(T_*I_/4 + 255)/256, 256>>>();

    // 5. shared expert: down GEMM  [T,I] x [H,I]^T -> [T,H]
    mma_gemm_tn<false,false,false><<<dim3(H_/128, T_/128, 1), 256>>>(
        p_sact, I_, s_wdn, I_, 0, p_sy, H_, T_, p_cnt, p_tok, p_dst, I_);

    // 6. routed gate_up: gather tokens per expert, scatter to pair slots
    mma_gemm_tn<true,true,true><<<dim3(TWOI_/128, T_/128, E_), 256>>>(
        x, H_, w_gu, H_, (long)TWOI_*H_, p_gu, TWOI_, 0, p_cnt, p_tok, p_dst, H_);

    // 7. routed silu*mul*weight
    silu_routed_kernel<<<(NPAIR_*I_/4 + 255)/256, 256>>>();

    // 8. routed down: gather act rows by slot, scatter outputs by slot
    mma_gemm_tn<true,true,true><<<dim3(H_/128, T_/128, E_), 256>>>(
        p_act, I_, w_dn, I_, (long)H_*I_, p_yrt, H_, 0, p_cnt, p_dst, p_dst, I_);

    // 9. combine: out = shared + 2.5 * sum_k routed
    reduce_kernel<<<(T_*H_/4 + 255)/256, 256>>>(out);
}